// round 12
// baseline (speedup 1.0000x reference)
#include <cuda_runtime.h>

// ---------------------------------------------------------------------------
// JPEG 8x8 DCT-II + luminance quantization, fused, two-phase via SMEM.
//
// image:  [16, 1, 1024, 1024] f32
// qf:     [16] f32
// out:    [16, 64, 128, 128] f32   (channel = u*8 + v)
//
// R12: CTA of 256 threads processes 32 blocks (same b, bi; consecutive bj).
//   Phase 1: thread (row, blk) loads one 8-float row, row-DCT, -> SMEM.
//   Phase 2: thread (col, blk) reads one column from SMEM, column-DCT,
//            quantizes, stores 8 STG.32 (lanes vary bj -> 128B/line each).
// Live set per thread ~10 floats -> high occupancy, short dep chains,
// full-warp-coalesced loads AND stores.
// ---------------------------------------------------------------------------

// Butterfly coefficients (orthonormal DCT-II, a[k] folded in).
#define A0f 0.35355339059327373f   /* a0 ; also a4*cos(pi/4) */
#define B1f 0.46193976625564337f   /* 0.5*cos(pi/8)   */
#define B3f 0.19134171618254492f   /* 0.5*cos(3pi/8)  */
#define G0f 0.49039264020161522f   /* 0.5*cos(pi/16)  */
#define G1f 0.41573480615127262f   /* 0.5*cos(3pi/16) */
#define G2f 0.27778511650980114f   /* 0.5*cos(5pi/16) */
#define G3f 0.09754516100806412f   /* 0.5*cos(7pi/16) */

// 8-point orthonormal DCT-II, in: x[8], out: y[8]. All coeffs immediates.
__device__ __forceinline__ void dct8(const float* x, float* y)
{
    const float s0 = x[0] + x[7], s1 = x[1] + x[6], s2 = x[2] + x[5], s3 = x[3] + x[4];
    const float d0 = x[0] - x[7], d1 = x[1] - x[6], d2 = x[2] - x[5], d3 = x[3] - x[4];

    const float t0 = s0 + s3, t1 = s1 + s2;
    const float u0 = s0 - s3, u1 = s1 - s2;

    y[0] = A0f * (t0 + t1);
    y[4] = A0f * (t0 - t1);
    y[2] = fmaf(B3f, u1, B1f * u0);
    y[6] = fmaf(-B1f, u1, B3f * u0);

    y[1] = fmaf(G3f, d3, fmaf(G2f, d2, fmaf(G1f, d1, G0f * d0)));
    y[3] = fmaf(-G2f, d3, fmaf(-G0f, d2, fmaf(-G3f, d1, G1f * d0)));
    y[5] = fmaf( G1f, d3, fmaf( G3f, d2, fmaf(-G0f, d1, G2f * d0)));
    y[7] = fmaf(-G0f, d3, fmaf( G1f, d2, fmaf(-G2f, d1, G3f * d0)));
}

// INVQ[u][v] = 100 / Q[u][v]; phase-2 index [u][col] is warp-uniform -> LDC.
__constant__ float INVQ[8][8] = {
    { 100.f/16.f, 100.f/11.f, 100.f/10.f, 100.f/16.f, 100.f/24.f, 100.f/40.f, 100.f/51.f,  100.f/61.f  },
    { 100.f/12.f, 100.f/12.f, 100.f/14.f, 100.f/19.f, 100.f/26.f, 100.f/58.f, 100.f/60.f,  100.f/55.f  },
    { 100.f/14.f, 100.f/13.f, 100.f/16.f, 100.f/24.f, 100.f/40.f, 100.f/57.f, 100.f/69.f,  100.f/56.f  },
    { 100.f/14.f, 100.f/17.f, 100.f/22.f, 100.f/29.f, 100.f/51.f, 100.f/87.f, 100.f/80.f,  100.f/62.f  },
    { 100.f/18.f, 100.f/22.f, 100.f/37.f, 100.f/56.f, 100.f/68.f, 100.f/109.f,100.f/103.f, 100.f/77.f  },
    { 100.f/24.f, 100.f/36.f, 100.f/55.f, 100.f/64.f, 100.f/81.f, 100.f/104.f,100.f/113.f, 100.f/92.f  },
    { 100.f/49.f, 100.f/64.f, 100.f/78.f, 100.f/87.f, 100.f/103.f,100.f/121.f,100.f/120.f, 100.f/101.f },
    { 100.f/72.f, 100.f/92.f, 100.f/95.f, 100.f/98.f, 100.f/112.f,100.f/100.f,100.f/103.f, 100.f/99.f  },
};

static constexpr int BATCH   = 16;
static constexpr int NBI     = 128;     // 1024/8 block rows
static constexpr int NBJ     = 128;     // 1024/8 block cols
static constexpr int BLKS_PER_CTA = 32; // consecutive bj
static constexpr int TPB     = 256;     // 8 threads per 8x8 block
static constexpr int NCTAS   = BATCH * NBI * (NBJ / BLKS_PER_CTA);  // 8192
static constexpr int SM_STRIDE = 65;    // floats per block in SMEM (pad)

__global__ void __launch_bounds__(TPB)
jpeg_dct_quant_kernel(const float* __restrict__ img,
                      const float* __restrict__ qf,
                      float* __restrict__ out)
{
    __shared__ float sm[BLKS_PER_CTA * SM_STRIDE];   // 8320 B

    // CTA -> (b, bi, bj tile of 32)
    const int t  = blockIdx.x & 3;
    const int bi = (blockIdx.x >> 2) & 127;
    const int b  = blockIdx.x >> 9;

    const int lane = threadIdx.x & 31;   // blk within tile (phase 1 & 2)
    const int wrow = threadIdx.x >> 5;   // row (phase 1) / col (phase 2)

    // ---- per-batch quality factor -> single reciprocal scale ----
    const float q      = qf[b];
    const float factor = (q < 50.0f) ? (5000.0f / q) : (200.0f - 2.0f * q);
    const float invF   = 1.0f / factor;
    const float negC   = -128.0f * invF;           // centering folded with invF

    const int bj = (t << 5) + lane;                // this thread's block col

    // ================= phase 1: load row, row-DCT, -> SMEM =================
    {
        const int row = wrow;
        const float* src = img + ((size_t)b << 20)
                               + ((size_t)((bi << 3) + row) << 10)
                               + (bj << 3);
        // warp = fixed row, 32 consecutive blocks: each LDG.128 covers 1KB
        const float4 lo = *reinterpret_cast<const float4*>(src);
        const float4 hi = *reinterpret_cast<const float4*>(src + 4);

        float x[8], y[8];
        x[0] = fmaf(lo.x, invF, negC); x[1] = fmaf(lo.y, invF, negC);
        x[2] = fmaf(lo.z, invF, negC); x[3] = fmaf(lo.w, invF, negC);
        x[4] = fmaf(hi.x, invF, negC); x[5] = fmaf(hi.y, invF, negC);
        x[6] = fmaf(hi.z, invF, negC); x[7] = fmaf(hi.w, invF, negC);

        dct8(x, y);

        // sm[blk][row][v], blk stride 65 -> lanes hit distinct banks
        float* dstm = &sm[lane * SM_STRIDE + (row << 3)];
#pragma unroll
        for (int v = 0; v < 8; ++v) dstm[v] = y[v];
    }

    __syncthreads();

    // ========== phase 2: column-DCT from SMEM, quantize, store ==========
    {
        const int col = wrow;                      // warp-uniform v
        const float* srcm = &sm[lane * SM_STRIDE + col];

        float x[8], y[8];
#pragma unroll
        for (int r = 0; r < 8; ++r) x[r] = srcm[r << 3];   // stride 65 across lanes

        dct8(x, y);

        // out[b][u*8+col][bi][bj]; lanes vary bj -> 128B line per STG
        float* dst = out + ((size_t)b << 20) + (bi << 7) + bj
                         + ((size_t)col << 14);
#pragma unroll
        for (int u = 0; u < 8; ++u)
            __stcs(&dst[(size_t)(u << 3) << 14], y[u] * INVQ[u][col]);
    }
}

extern "C" void kernel_launch(void* const* d_in, const int* in_sizes, int n_in,
                              void* d_out, int out_size)
{
    (void)in_sizes; (void)n_in; (void)out_size;
    const float* img = (const float*)d_in[0];
    const float* qf  = (const float*)d_in[1];
    float*       out = (float*)d_out;

    jpeg_dct_quant_kernel<<<NCTAS, TPB>>>(img, qf, out);
}

// round 13
// speedup vs baseline: 1.1931x; 1.1931x over previous
#include <cuda_runtime.h>

// ---------------------------------------------------------------------------
// JPEG 8x8 DCT-II + luminance quantization, fused, one thread per 8x8 block.
//
// image:  [16, 1, 1024, 1024] f32
// qf:     [16] f32
// out:    [16, 64, 128, 128] f32   (channel = u*8 + v)
//
// R13: R9 body (best structure: per-thread block, butterfly DCT, folded
// centering*invF, coalesced STG.32 + __stcs) wrapped in a balanced
// 2-iteration grid-stride loop. TPB=128, grid=1024 -> ~1.15 CTA waves
// instead of 2.8, eliminating wave-transition DRAM idle gaps.
// ---------------------------------------------------------------------------

// Butterfly coefficients (orthonormal DCT-II, a[k] folded in; a0=1/(2*sqrt2),
// a[k>0]=1/2). Literals round to the exact f32 values of the f64 reference.
#define A0f 0.35355339059327373f   /* a0 ; also a4*cos(pi/4) */
#define B1f 0.46193976625564337f   /* 0.5*cos(pi/8)   */
#define B3f 0.19134171618254492f   /* 0.5*cos(3pi/8)  */
#define G0f 0.49039264020161522f   /* 0.5*cos(pi/16)  */
#define G1f 0.41573480615127262f   /* 0.5*cos(3pi/16) */
#define G2f 0.27778511650980114f   /* 0.5*cos(5pi/16) */
#define G3f 0.09754516100806412f   /* 0.5*cos(7pi/16) */

// 8-point orthonormal DCT-II, in place, compile-time stride S (registers only
// after inlining: all indices constant).
template <int S>
__device__ __forceinline__ void dct8(float* p)
{
    const float x0 = p[0*S], x1 = p[1*S], x2 = p[2*S], x3 = p[3*S];
    const float x4 = p[4*S], x5 = p[5*S], x6 = p[6*S], x7 = p[7*S];

    const float s0 = x0 + x7, s1 = x1 + x6, s2 = x2 + x5, s3 = x3 + x4;
    const float d0 = x0 - x7, d1 = x1 - x6, d2 = x2 - x5, d3 = x3 - x4;

    const float t0 = s0 + s3, t1 = s1 + s2;
    const float u0 = s0 - s3, u1 = s1 - s2;

    p[0*S] = A0f * (t0 + t1);
    p[4*S] = A0f * (t0 - t1);
    p[2*S] = fmaf(B3f, u1, B1f * u0);
    p[6*S] = fmaf(-B1f, u1, B3f * u0);

    p[1*S] = fmaf(G3f, d3, fmaf(G2f, d2, fmaf(G1f, d1, G0f * d0)));
    p[3*S] = fmaf(-G2f, d3, fmaf(-G0f, d2, fmaf(-G3f, d1, G1f * d0)));
    p[5*S] = fmaf( G1f, d3, fmaf( G3f, d2, fmaf(-G0f, d1, G2f * d0)));
    p[7*S] = fmaf(-G0f, d3, fmaf( G1f, d2, fmaf(-G2f, d1, G3f * d0)));
}

// INVQ[u][v] = 100 / Q[u][v]  (reference divides by Q/100; we multiply by 100/Q)
__device__ constexpr float INVQ[8][8] = {
    { 100.f/16.f, 100.f/11.f, 100.f/10.f, 100.f/16.f, 100.f/24.f, 100.f/40.f, 100.f/51.f,  100.f/61.f  },
    { 100.f/12.f, 100.f/12.f, 100.f/14.f, 100.f/19.f, 100.f/26.f, 100.f/58.f, 100.f/60.f,  100.f/55.f  },
    { 100.f/14.f, 100.f/13.f, 100.f/16.f, 100.f/24.f, 100.f/40.f, 100.f/57.f, 100.f/69.f,  100.f/56.f  },
    { 100.f/14.f, 100.f/17.f, 100.f/22.f, 100.f/29.f, 100.f/51.f, 100.f/87.f, 100.f/80.f,  100.f/62.f  },
    { 100.f/18.f, 100.f/22.f, 100.f/37.f, 100.f/56.f, 100.f/68.f, 100.f/109.f,100.f/103.f, 100.f/77.f  },
    { 100.f/24.f, 100.f/36.f, 100.f/55.f, 100.f/64.f, 100.f/81.f, 100.f/104.f,100.f/113.f, 100.f/92.f  },
    { 100.f/49.f, 100.f/64.f, 100.f/78.f, 100.f/87.f, 100.f/103.f,100.f/121.f,100.f/120.f, 100.f/101.f },
    { 100.f/72.f, 100.f/92.f, 100.f/95.f, 100.f/98.f, 100.f/112.f,100.f/100.f,100.f/103.f, 100.f/99.f  },
};

static constexpr int BATCH   = 16;
static constexpr int HEIGHT  = 1024;
static constexpr int WIDTH   = 1024;
static constexpr int NBI     = HEIGHT / 8;          // 128 block rows
static constexpr int NBJ     = WIDTH / 8;           // 128 block cols
static constexpr int NBLOCKS = BATCH * NBI * NBJ;   // 262144
static constexpr int TPB     = 128;
static constexpr int GRID    = 1024;                // 1024*128*2 == NBLOCKS
static constexpr int STRIDE  = GRID * TPB;          // 131072
static constexpr int ITERS   = NBLOCKS / STRIDE;    // 2

__global__ void __launch_bounds__(TPB)
jpeg_dct_quant_kernel(const float* __restrict__ img,
                      const float* __restrict__ qf,
                      float* __restrict__ out)
{
    const int tid0 = blockIdx.x * TPB + threadIdx.x;

#pragma unroll 1
    for (int it = 0; it < ITERS; ++it) {
        const int blk = tid0 + it * STRIDE;

        // blk -> (b, block_i, block_j); lanes in a warp get consecutive bj
        const int b   = blk >> 14;          // / 16384
        const int rem = blk & 16383;
        const int bi  = rem >> 7;           // / 128
        const int bj  = rem & 127;

        // ---- per-batch quality factor -> single reciprocal scale ----
        const float q      = qf[b];
        const float factor = (q < 50.0f) ? (5000.0f / q) : (200.0f - 2.0f * q);
        const float invF   = 1.0f / factor;
        const float negC   = -128.0f * invF;   // centering folded with invF

        // ---- load 8x8 pixel block; x = p*invF - 128*invF (one FFMA each) ----
        const float* src = img + ((size_t)b << 20) + ((size_t)(bi << 3) << 10) + (bj << 3);

        float x[8][8];
#pragma unroll
        for (int r = 0; r < 8; ++r) {
            const float4 lo = *reinterpret_cast<const float4*>(src + ((size_t)r << 10));
            const float4 hi = *reinterpret_cast<const float4*>(src + ((size_t)r << 10) + 4);
            x[r][0] = fmaf(lo.x, invF, negC); x[r][1] = fmaf(lo.y, invF, negC);
            x[r][2] = fmaf(lo.z, invF, negC); x[r][3] = fmaf(lo.w, invF, negC);
            x[r][4] = fmaf(hi.x, invF, negC); x[r][5] = fmaf(hi.y, invF, negC);
            x[r][6] = fmaf(hi.z, invF, negC); x[r][7] = fmaf(hi.w, invF, negC);
        }

        // ---- separable DCT: rows then columns, butterfly form ----
#pragma unroll
        for (int r = 0; r < 8; ++r)
            dct8<1>(&x[r][0]);
#pragma unroll
        for (int v = 0; v < 8; ++v)
            dct8<8>(&x[0][v]);

        // ---- quantize + store ----
        // out[b][u*8+v][bi][bj]; channel stride = 128*128 = 16384 elements.
        float* dst = out + ((size_t)b << 20) + (bi << 7) + bj;

#pragma unroll
        for (int u = 0; u < 8; ++u) {
#pragma unroll
            for (int v = 0; v < 8; ++v) {
                // one contiguous 128B line across the warp per STG (lanes
                // vary bj); evict-first since output is never re-read
                __stcs(&dst[(size_t)((u << 3) + v) << 14], x[u][v] * INVQ[u][v]);
            }
        }
    }
}

extern "C" void kernel_launch(void* const* d_in, const int* in_sizes, int n_in,
                              void* d_out, int out_size)
{
    (void)in_sizes; (void)n_in; (void)out_size;
    const float* img = (const float*)d_in[0];
    const float* qf  = (const float*)d_in[1];
    float*       out = (float*)d_out;

    jpeg_dct_quant_kernel<<<GRID, TPB>>>(img, qf, out);
}